// round 5
// baseline (speedup 1.0000x reference)
#include <cuda_runtime.h>

#define MAXN 100000
#define MAXE 1600000
#define FIN 128
#define FH 64
#define FO 16

// Scratch (device globals: allocation-free, sanctioned by harness rules)
__device__ int    g_is64;            // 1 if edge_index is int64, 0 if int32
__device__ float  g_dinv[MAXN];
__device__ int    g_cnt[MAXN];       // in-degree (edges only)
__device__ int    g_rowstart[MAXN];  // CSR row offsets (by dst)
__device__ int    g_cursor[MAXN];    // fill cursors
__device__ int    g_csrc[MAXE];      // CSR: source node per slot
__device__ float  g_cnorm[MAXE];     // CSR: raw ew, then final norm
__device__ float4 g_h1[(size_t)MAXN * (FH / 4)];  // x @ W1        [n][64]
__device__ float4 g_z [(size_t)MAXN * (FH / 4)];  // relu(agg1)    [n][64]
__device__ float4 g_h2[(size_t)MAXN * (FO / 4)];  // z @ W2        [n][16]

__device__ __forceinline__ int edge_src(const void* ei, int E, int e) {
    return g_is64 ? (int)((const long long*)ei)[e] : ((const int*)ei)[e];
}
__device__ __forceinline__ int edge_dst(const void* ei, int E, int e) {
    return g_is64 ? (int)((const long long*)ei)[(size_t)E + e]
                  : ((const int*)ei)[(size_t)E + e];
}

// ---------------------------------------------------------------------------
// probe: decide int32 vs int64 by plausibility of values read as int64.
// Packed int32 pairs read as int64 are >= 2^32 (or negative) w.h.p.
// ---------------------------------------------------------------------------
__global__ void probe_kernel(const void* ei, int E, int n) {
    if (threadIdx.x != 0 || blockIdx.x != 0) return;
    const long long* p = (const long long*)ei;
    int ok64 = 1;
    int m = E < 64 ? E : 64;
    for (int i = 0; i < m; i++) {
        long long v = p[i];
        long long w = p[(size_t)E + i];
        if (v < 0 || v >= n || w < 0 || w >= n) { ok64 = 0; break; }
    }
    g_is64 = ok64;
}

__global__ void init_kernel(int n) {
    int i = blockIdx.x * blockDim.x + threadIdx.x;
    if (i < n) g_cnt[i] = 0;
}

// edge count per dst (int atomics only)
__global__ void cnt_kernel(const void* __restrict__ ei, int E) {
    int e = blockIdx.x * blockDim.x + threadIdx.x;
    if (e >= E) return;
    atomicAdd(&g_cnt[edge_dst(ei, E, e)], 1);
}

// single-block exclusive scan of g_cnt -> g_rowstart (+ cursor copy)
__global__ void scan_kernel(int n) {
    __shared__ int ssum[1024];
    int t = threadIdx.x;
    int C = (n + 1023) / 1024;
    int lo = t * C, hi = min(lo + C, n);
    int s = 0;
    for (int i = lo; i < hi; i++) s += g_cnt[i];
    ssum[t] = s;
    __syncthreads();
    for (int off = 1; off < 1024; off <<= 1) {
        int v = (t >= off) ? ssum[t - off] : 0;
        __syncthreads();
        ssum[t] += v;
        __syncthreads();
    }
    int run = (t == 0) ? 0 : ssum[t - 1];
    for (int i = lo; i < hi; i++) {
        g_rowstart[i] = run;
        g_cursor[i] = run;
        run += g_cnt[i];
    }
}

// scatter edges into CSR slots (int atomic cursors); store src + raw weight
__global__ void build_kernel(const void* __restrict__ ei,
                             const float* __restrict__ ew, int E) {
    int e = blockIdx.x * blockDim.x + threadIdx.x;
    if (e >= E) return;
    int s = edge_src(ei, E, e);
    int d = edge_dst(ei, E, e);
    int pos = atomicAdd(&g_cursor[d], 1);
    g_csrc[pos] = s;
    g_cnorm[pos] = ew[e];
}

// warp per node: deg = 1 (self-loop) + sum of edge weights -> dinv (no atomics)
__global__ void dinv_kernel(int n) {
    int warp = (blockIdx.x * blockDim.x + threadIdx.x) >> 5;
    if (warp >= n) return;
    int lane = threadIdx.x & 31;
    int start = g_rowstart[warp];
    int end = start + g_cnt[warp];
    float s = 0.f;
    for (int j = start + lane; j < end; j += 32) s += g_cnorm[j];
    #pragma unroll
    for (int off = 16; off > 0; off >>= 1)
        s += __shfl_xor_sync(0xffffffffu, s, off);
    if (lane == 0) g_dinv[warp] = rsqrtf(1.0f + s);
}

// warp per node: cnorm[j] = dinv[src] * ew * dinv[dst]
__global__ void norm_kernel(int n) {
    int warp = (blockIdx.x * blockDim.x + threadIdx.x) >> 5;
    if (warp >= n) return;
    int lane = threadIdx.x & 31;
    float dd = g_dinv[warp];
    int start = g_rowstart[warp];
    int end = start + g_cnt[warp];
    for (int j = start + lane; j < end; j += 32)
        g_cnorm[j] = g_dinv[g_csrc[j]] * g_cnorm[j] * dd;
}

// ---------------------------------------------------------------------------
// h1 = x @ W1   (n x 128 @ 128 x 64), 16 rows/block, 256 threads, 40KB smem
// ---------------------------------------------------------------------------
__global__ void gemm1_kernel(const float* __restrict__ x,
                             const float* __restrict__ W1, int n) {
    __shared__ float sW[FIN * FH];   // 32 KB
    __shared__ float sx[16][FIN];    //  8 KB
    int t = threadIdx.x;
    const float4* w4 = (const float4*)W1;
    float4* sw4 = (float4*)sW;
    #pragma unroll
    for (int i = t; i < FIN * FH / 4; i += 256) sw4[i] = w4[i];

    int rowBase = blockIdx.x * 16;
    for (int i = t; i < 16 * FIN / 4; i += 256) {
        int r = i / (FIN / 4), c = i % (FIN / 4);
        int row = rowBase + r;
        float4 val = (row < n) ? ((const float4*)(x + (size_t)row * FIN))[c]
                               : make_float4(0.f, 0.f, 0.f, 0.f);
        ((float4*)&sx[r][0])[c] = val;
    }
    __syncthreads();

    int col = t & 63;
    int rg = t >> 6;  // 0..3 -> rows rg*4 .. rg*4+3
    float acc[4];
    #pragma unroll
    for (int i = 0; i < 4; i++) acc[i] = 0.f;
    #pragma unroll
    for (int k4 = 0; k4 < FIN / 4; k4++) {
        float w0 = sW[(k4 * 4 + 0) * FH + col];
        float w1 = sW[(k4 * 4 + 1) * FH + col];
        float w2 = sW[(k4 * 4 + 2) * FH + col];
        float w3 = sW[(k4 * 4 + 3) * FH + col];
        #pragma unroll
        for (int i = 0; i < 4; i++) {
            float4 xv = ((const float4*)&sx[rg * 4 + i][0])[k4];
            acc[i] += xv.x * w0 + xv.y * w1 + xv.z * w2 + xv.w * w3;
        }
    }
    float* h1 = (float*)g_h1;
    #pragma unroll
    for (int i = 0; i < 4; i++) {
        int row = rowBase + rg * 4 + i;
        if (row < n) h1[(size_t)row * FH + col] = acc[i];
    }
}

// ---------------------------------------------------------------------------
// agg1: one warp per dst node. Lanes own 2 features (float2 of the 64).
// z[d] = relu( sum_e norm_e * h1[src_e] + dinv[d]^2 * h1[d] + b1 )
// ---------------------------------------------------------------------------
__global__ void agg1_kernel(const float* __restrict__ b1, int n) {
    int warp = (blockIdx.x * blockDim.x + threadIdx.x) >> 5;
    if (warp >= n) return;
    int lane = threadIdx.x & 31;
    const float2* h1 = (const float2*)g_h1;   // [n][32] float2
    int start = g_rowstart[warp];
    int end = start + g_cnt[warp];
    float2 acc = make_float2(0.f, 0.f);

    int j = start;
    for (; j + 4 <= end; j += 4) {
        int   s0 = g_csrc[j],  s1 = g_csrc[j+1],  s2 = g_csrc[j+2],  s3 = g_csrc[j+3];
        float n0 = g_cnorm[j], n1 = g_cnorm[j+1], n2 = g_cnorm[j+2], n3 = g_cnorm[j+3];
        float2 v0 = h1[(size_t)s0 * 32 + lane];
        float2 v1 = h1[(size_t)s1 * 32 + lane];
        float2 v2 = h1[(size_t)s2 * 32 + lane];
        float2 v3 = h1[(size_t)s3 * 32 + lane];
        acc.x += n0 * v0.x + n1 * v1.x + n2 * v2.x + n3 * v3.x;
        acc.y += n0 * v0.y + n1 * v1.y + n2 * v2.y + n3 * v3.y;
    }
    for (; j < end; j++) {
        int s = g_csrc[j];
        float nm = g_cnorm[j];
        float2 v = h1[(size_t)s * 32 + lane];
        acc.x += nm * v.x;
        acc.y += nm * v.y;
    }
    // self loop
    float dv = g_dinv[warp];
    float self = dv * dv;
    float2 hs = h1[(size_t)warp * 32 + lane];
    acc.x += self * hs.x;
    acc.y += self * hs.y;
    // bias + relu
    acc.x = fmaxf(acc.x + b1[lane * 2 + 0], 0.f);
    acc.y = fmaxf(acc.y + b1[lane * 2 + 1], 0.f);
    ((float2*)g_z)[(size_t)warp * 32 + lane] = acc;
}

// ---------------------------------------------------------------------------
// h2 = z @ W2  (64 -> 16), one thread per node, W2 in SMEM
// ---------------------------------------------------------------------------
__global__ void gemm2_kernel(const float* __restrict__ W2, int n) {
    __shared__ float sW[FH * FO];  // 4 KB
    for (int i = threadIdx.x; i < FH * FO; i += blockDim.x) sW[i] = W2[i];
    __syncthreads();

    int nn = blockIdx.x * blockDim.x + threadIdx.x;
    if (nn >= n) return;
    const float4* z4 = &g_z[(size_t)nn * (FH / 4)];
    float acc[FO];
    #pragma unroll
    for (int j = 0; j < FO; j++) acc[j] = 0.f;
    #pragma unroll
    for (int k4 = 0; k4 < FH / 4; k4++) {
        float4 zv = z4[k4];
        #pragma unroll
        for (int j = 0; j < FO; j++) {
            acc[j] += zv.x * sW[(k4 * 4 + 0) * FO + j];
            acc[j] += zv.y * sW[(k4 * 4 + 1) * FO + j];
            acc[j] += zv.z * sW[(k4 * 4 + 2) * FO + j];
            acc[j] += zv.w * sW[(k4 * 4 + 3) * FO + j];
        }
    }
    float4* o4 = &g_h2[(size_t)nn * (FO / 4)];
    o4[0] = make_float4(acc[0], acc[1], acc[2], acc[3]);
    o4[1] = make_float4(acc[4], acc[5], acc[6], acc[7]);
    o4[2] = make_float4(acc[8], acc[9], acc[10], acc[11]);
    o4[3] = make_float4(acc[12], acc[13], acc[14], acc[15]);
}

// ---------------------------------------------------------------------------
// agg2 + log_softmax: half-warp (16 lanes) per node, one feature per lane.
// ---------------------------------------------------------------------------
__global__ void agg2_kernel(const float* __restrict__ b2,
                            float* __restrict__ out, int n) {
    int gid = blockIdx.x * blockDim.x + threadIdx.x;
    int node = gid >> 4;
    bool live = node < n;
    if (!live) node = 0;              // keep lanes active for shuffles
    int f = gid & 15;
    const float* h2 = (const float*)g_h2;   // [n][16]
    int start = g_rowstart[node];
    int end = start + g_cnt[node];
    float acc = 0.f;

    int j = start;
    for (; j + 4 <= end; j += 4) {
        int   s0 = g_csrc[j],  s1 = g_csrc[j+1],  s2 = g_csrc[j+2],  s3 = g_csrc[j+3];
        float n0 = g_cnorm[j], n1 = g_cnorm[j+1], n2 = g_cnorm[j+2], n3 = g_cnorm[j+3];
        acc += n0 * h2[(size_t)s0 * FO + f] + n1 * h2[(size_t)s1 * FO + f]
             + n2 * h2[(size_t)s2 * FO + f] + n3 * h2[(size_t)s3 * FO + f];
    }
    for (; j < end; j++) {
        acc += g_cnorm[j] * h2[(size_t)g_csrc[j] * FO + f];
    }
    float dv = g_dinv[node];
    acc += dv * dv * h2[(size_t)node * FO + f] + b2[f];

    // log_softmax over the 16 lanes of this half-warp
    float m = acc;
    #pragma unroll
    for (int off = 8; off > 0; off >>= 1)
        m = fmaxf(m, __shfl_xor_sync(0xffffffffu, m, off));
    float e = expf(acc - m);
    float ssum = e;
    #pragma unroll
    for (int off = 8; off > 0; off >>= 1)
        ssum += __shfl_xor_sync(0xffffffffu, ssum, off);
    if (live) out[(size_t)node * FO + f] = acc - m - logf(ssum);
}

// ---------------------------------------------------------------------------
extern "C" void kernel_launch(void* const* d_in, const int* in_sizes, int n_in,
                              void* d_out, int out_size) {
    const float* x  = (const float*)d_in[0];
    const void*  ei = d_in[1];               // [2, E]; int32 or int64 (probed)
    const float* ew = (const float*)d_in[2];
    const float* W1 = (const float*)d_in[3];
    const float* b1 = (const float*)d_in[4];
    const float* W2 = (const float*)d_in[5];
    const float* b2 = (const float*)d_in[6];
    float*       out = (float*)d_out;

    int n = in_sizes[0] / FIN;   // 100000
    int E = in_sizes[2];         // 1600000 (edge_weights count, dtype-safe)

    probe_kernel<<<1, 1>>>(ei, E, n);
    init_kernel<<<(n + 255) / 256, 256>>>(n);
    cnt_kernel<<<(E + 255) / 256, 256>>>(ei, E);
    scan_kernel<<<1, 1024>>>(n);
    build_kernel<<<(E + 255) / 256, 256>>>(ei, ew, E);

    long long tw = (long long)n * 32;  // one warp per node
    dinv_kernel<<<(int)((tw + 255) / 256), 256>>>(n);
    norm_kernel<<<(int)((tw + 255) / 256), 256>>>(n);

    gemm1_kernel<<<(n + 15) / 16, 256>>>(x, W1, n);

    agg1_kernel<<<(int)((tw + 255) / 256), 256>>>(b1, n);

    gemm2_kernel<<<(n + 255) / 256, 256>>>(W2, n);

    long long t2 = (long long)n * 16;
    agg2_kernel<<<(int)((t2 + 255) / 256), 256>>>(b2, out, n);
}

// round 6
// speedup vs baseline: 1.6354x; 1.6354x over previous
#include <cuda_runtime.h>

#define MAXN 100000
#define MAXE 1600000
#define FIN 128
#define FH 64
#define FO 16
#define SCAN_B 1024
#define MAXBLK 128   // >= ceil(MAXN/SCAN_B)

// Scratch (device globals: allocation-free)
__device__ int    g_is64;            // 1 if edge_index is int64, 0 if int32
__device__ float  g_dinv[MAXN];
__device__ int    g_cnt[MAXN];       // in-degree (edges only)
__device__ int    g_rowstart[MAXN];  // CSR row offsets (by dst)
__device__ int    g_cursor[MAXN];    // fill cursors
__device__ int    g_blocksum[MAXBLK];
__device__ int    g_csrc[MAXE];      // CSR: source node per slot
__device__ float  g_cnorm[MAXE];     // CSR: raw ew, then final norm
__device__ float4 g_h1[(size_t)MAXN * (FH / 4)];  // x @ W1        [n][64]
__device__ float4 g_z [(size_t)MAXN * (FH / 4)];  // relu(agg1)    [n][64]
__device__ float4 g_h2[(size_t)MAXN * (FO / 4)];  // z @ W2        [n][16]

__device__ __forceinline__ int edge_src(const void* ei, int E, int e) {
    return g_is64 ? (int)((const long long*)ei)[e] : ((const int*)ei)[e];
}
__device__ __forceinline__ int edge_dst(const void* ei, int E, int e) {
    return g_is64 ? (int)((const long long*)ei)[(size_t)E + e]
                  : ((const int*)ei)[(size_t)E + e];
}

// ---------------------------------------------------------------------------
// probe: int32 vs int64 by plausibility of values read as int64.
// ---------------------------------------------------------------------------
__global__ void probe_kernel(const void* ei, int E, int n) {
    if (threadIdx.x != 0 || blockIdx.x != 0) return;
    const long long* p = (const long long*)ei;
    int ok64 = 1;
    int m = E < 64 ? E : 64;
    for (int i = 0; i < m; i++) {
        long long v = p[i];
        long long w = p[(size_t)E + i];
        if (v < 0 || v >= n || w < 0 || w >= n) { ok64 = 0; break; }
    }
    g_is64 = ok64;
}

__global__ void init_kernel(int n) {
    int i = blockIdx.x * blockDim.x + threadIdx.x;
    if (i < n) g_cnt[i] = 0;
}

// edge count per dst (int atomics only)
__global__ void cnt_kernel(const void* __restrict__ ei, int E) {
    int e = blockIdx.x * blockDim.x + threadIdx.x;
    if (e >= E) return;
    atomicAdd(&g_cnt[edge_dst(ei, E, e)], 1);
}

// ---------------------------------------------------------------------------
// hierarchical exclusive scan of g_cnt -> g_rowstart (+ cursor copy)
// ---------------------------------------------------------------------------
__global__ void scan1_kernel(int n) {     // per-block inclusive scan in smem
    __shared__ int s[SCAN_B];
    int t = threadIdx.x;
    int gid = blockIdx.x * SCAN_B + t;
    int v = (gid < n) ? g_cnt[gid] : 0;
    s[t] = v;
    __syncthreads();
    #pragma unroll
    for (int off = 1; off < SCAN_B; off <<= 1) {
        int u = (t >= off) ? s[t - off] : 0;
        __syncthreads();
        s[t] += u;
        __syncthreads();
    }
    if (gid < n) g_rowstart[gid] = s[t] - v;   // block-local exclusive
    if (t == SCAN_B - 1) g_blocksum[blockIdx.x] = s[t];
}

__global__ void scan2_kernel(int nb) {    // exclusive scan of block sums
    __shared__ int s[MAXBLK];
    int t = threadIdx.x;
    int v = (t < nb) ? g_blocksum[t] : 0;
    s[t] = v;
    __syncthreads();
    #pragma unroll
    for (int off = 1; off < MAXBLK; off <<= 1) {
        int u = (t >= off) ? s[t - off] : 0;
        __syncthreads();
        s[t] += u;
        __syncthreads();
    }
    if (t < nb) g_blocksum[t] = s[t] - v;
}

__global__ void scan3_kernel(int n) {     // add block offsets, fill cursor
    int gid = blockIdx.x * blockDim.x + threadIdx.x;
    if (gid >= n) return;
    int r = g_rowstart[gid] + g_blocksum[gid >> 10];
    g_rowstart[gid] = r;
    g_cursor[gid] = r;
}

// scatter edges into CSR slots (int atomic cursors); store src + raw weight
__global__ void build_kernel(const void* __restrict__ ei,
                             const float* __restrict__ ew, int E) {
    int e = blockIdx.x * blockDim.x + threadIdx.x;
    if (e >= E) return;
    int s = edge_src(ei, E, e);
    int d = edge_dst(ei, E, e);
    int pos = atomicAdd(&g_cursor[d], 1);
    g_csrc[pos] = s;
    g_cnorm[pos] = ew[e];
}

// warp per node: deg = 1 (self-loop) + sum of edge weights -> dinv
__global__ void dinv_kernel(int n) {
    int warp = (blockIdx.x * blockDim.x + threadIdx.x) >> 5;
    if (warp >= n) return;
    int lane = threadIdx.x & 31;
    int start = g_rowstart[warp];
    int end = start + g_cnt[warp];
    float s = 0.f;
    for (int j = start + lane; j < end; j += 32) s += g_cnorm[j];
    #pragma unroll
    for (int off = 16; off > 0; off >>= 1)
        s += __shfl_xor_sync(0xffffffffu, s, off);
    if (lane == 0) g_dinv[warp] = rsqrtf(1.0f + s);
}

// warp per node: cnorm[j] = dinv[src] * ew * dinv[dst]
__global__ void norm_kernel(int n) {
    int warp = (blockIdx.x * blockDim.x + threadIdx.x) >> 5;
    if (warp >= n) return;
    int lane = threadIdx.x & 31;
    float dd = g_dinv[warp];
    int start = g_rowstart[warp];
    int end = start + g_cnt[warp];
    for (int j = start + lane; j < end; j += 32)
        g_cnorm[j] = g_dinv[g_csrc[j]] * g_cnorm[j] * dd;
}

// ---------------------------------------------------------------------------
// h1 = x @ W1   (n x 128 @ 128 x 64), 16 rows/block, 256 threads, 40KB smem
// ---------------------------------------------------------------------------
__global__ void gemm1_kernel(const float* __restrict__ x,
                             const float* __restrict__ W1, int n) {
    __shared__ float sW[FIN * FH];   // 32 KB
    __shared__ float sx[16][FIN];    //  8 KB
    int t = threadIdx.x;
    const float4* w4 = (const float4*)W1;
    float4* sw4 = (float4*)sW;
    #pragma unroll
    for (int i = t; i < FIN * FH / 4; i += 256) sw4[i] = w4[i];

    int rowBase = blockIdx.x * 16;
    for (int i = t; i < 16 * FIN / 4; i += 256) {
        int r = i / (FIN / 4), c = i % (FIN / 4);
        int row = rowBase + r;
        float4 val = (row < n) ? ((const float4*)(x + (size_t)row * FIN))[c]
                               : make_float4(0.f, 0.f, 0.f, 0.f);
        ((float4*)&sx[r][0])[c] = val;
    }
    __syncthreads();

    int col = t & 63;
    int rg = t >> 6;
    float acc[4];
    #pragma unroll
    for (int i = 0; i < 4; i++) acc[i] = 0.f;
    #pragma unroll
    for (int k4 = 0; k4 < FIN / 4; k4++) {
        float w0 = sW[(k4 * 4 + 0) * FH + col];
        float w1 = sW[(k4 * 4 + 1) * FH + col];
        float w2 = sW[(k4 * 4 + 2) * FH + col];
        float w3 = sW[(k4 * 4 + 3) * FH + col];
        #pragma unroll
        for (int i = 0; i < 4; i++) {
            float4 xv = ((const float4*)&sx[rg * 4 + i][0])[k4];
            acc[i] += xv.x * w0 + xv.y * w1 + xv.z * w2 + xv.w * w3;
        }
    }
    float* h1 = (float*)g_h1;
    #pragma unroll
    for (int i = 0; i < 4; i++) {
        int row = rowBase + rg * 4 + i;
        if (row < n) h1[(size_t)row * FH + col] = acc[i];
    }
}

// ---------------------------------------------------------------------------
// agg1: one warp per dst node. Lanes own 2 features (float2 of the 64).
// ---------------------------------------------------------------------------
__global__ void agg1_kernel(const float* __restrict__ b1, int n) {
    int warp = (blockIdx.x * blockDim.x + threadIdx.x) >> 5;
    if (warp >= n) return;
    int lane = threadIdx.x & 31;
    const float2* h1 = (const float2*)g_h1;   // [n][32] float2
    int start = g_rowstart[warp];
    int end = start + g_cnt[warp];
    float2 acc = make_float2(0.f, 0.f);

    int j = start;
    for (; j + 4 <= end; j += 4) {
        int   s0 = g_csrc[j],  s1 = g_csrc[j+1],  s2 = g_csrc[j+2],  s3 = g_csrc[j+3];
        float n0 = g_cnorm[j], n1 = g_cnorm[j+1], n2 = g_cnorm[j+2], n3 = g_cnorm[j+3];
        float2 v0 = h1[(size_t)s0 * 32 + lane];
        float2 v1 = h1[(size_t)s1 * 32 + lane];
        float2 v2 = h1[(size_t)s2 * 32 + lane];
        float2 v3 = h1[(size_t)s3 * 32 + lane];
        acc.x += n0 * v0.x + n1 * v1.x + n2 * v2.x + n3 * v3.x;
        acc.y += n0 * v0.y + n1 * v1.y + n2 * v2.y + n3 * v3.y;
    }
    for (; j < end; j++) {
        int s = g_csrc[j];
        float nm = g_cnorm[j];
        float2 v = h1[(size_t)s * 32 + lane];
        acc.x += nm * v.x;
        acc.y += nm * v.y;
    }
    float dv = g_dinv[warp];
    float self = dv * dv;
    float2 hs = h1[(size_t)warp * 32 + lane];
    acc.x += self * hs.x;
    acc.y += self * hs.y;
    acc.x = fmaxf(acc.x + b1[lane * 2 + 0], 0.f);
    acc.y = fmaxf(acc.y + b1[lane * 2 + 1], 0.f);
    ((float2*)g_z)[(size_t)warp * 32 + lane] = acc;
}

// ---------------------------------------------------------------------------
// h2 = z @ W2  (64 -> 16), one thread per node, W2 in SMEM
// ---------------------------------------------------------------------------
__global__ void gemm2_kernel(const float* __restrict__ W2, int n) {
    __shared__ float sW[FH * FO];  // 4 KB
    for (int i = threadIdx.x; i < FH * FO; i += blockDim.x) sW[i] = W2[i];
    __syncthreads();

    int nn = blockIdx.x * blockDim.x + threadIdx.x;
    if (nn >= n) return;
    const float4* z4 = &g_z[(size_t)nn * (FH / 4)];
    float acc[FO];
    #pragma unroll
    for (int j = 0; j < FO; j++) acc[j] = 0.f;
    #pragma unroll
    for (int k4 = 0; k4 < FH / 4; k4++) {
        float4 zv = z4[k4];
        #pragma unroll
        for (int j = 0; j < FO; j++) {
            acc[j] += zv.x * sW[(k4 * 4 + 0) * FO + j];
            acc[j] += zv.y * sW[(k4 * 4 + 1) * FO + j];
            acc[j] += zv.z * sW[(k4 * 4 + 2) * FO + j];
            acc[j] += zv.w * sW[(k4 * 4 + 3) * FO + j];
        }
    }
    float4* o4 = &g_h2[(size_t)nn * (FO / 4)];
    o4[0] = make_float4(acc[0], acc[1], acc[2], acc[3]);
    o4[1] = make_float4(acc[4], acc[5], acc[6], acc[7]);
    o4[2] = make_float4(acc[8], acc[9], acc[10], acc[11]);
    o4[3] = make_float4(acc[12], acc[13], acc[14], acc[15]);
}

// ---------------------------------------------------------------------------
// agg2 + log_softmax: half-warp (16 lanes) per node, one feature per lane.
// ---------------------------------------------------------------------------
__global__ void agg2_kernel(const float* __restrict__ b2,
                            float* __restrict__ out, int n) {
    int gid = blockIdx.x * blockDim.x + threadIdx.x;
    int node = gid >> 4;
    bool live = node < n;
    if (!live) node = 0;
    int f = gid & 15;
    const float* h2 = (const float*)g_h2;   // [n][16]
    int start = g_rowstart[node];
    int end = start + g_cnt[node];
    float acc = 0.f;

    int j = start;
    for (; j + 4 <= end; j += 4) {
        int   s0 = g_csrc[j],  s1 = g_csrc[j+1],  s2 = g_csrc[j+2],  s3 = g_csrc[j+3];
        float n0 = g_cnorm[j], n1 = g_cnorm[j+1], n2 = g_cnorm[j+2], n3 = g_cnorm[j+3];
        acc += n0 * h2[(size_t)s0 * FO + f] + n1 * h2[(size_t)s1 * FO + f]
             + n2 * h2[(size_t)s2 * FO + f] + n3 * h2[(size_t)s3 * FO + f];
    }
    for (; j < end; j++) {
        acc += g_cnorm[j] * h2[(size_t)g_csrc[j] * FO + f];
    }
    float dv = g_dinv[node];
    acc += dv * dv * h2[(size_t)node * FO + f] + b2[f];

    float m = acc;
    #pragma unroll
    for (int off = 8; off > 0; off >>= 1)
        m = fmaxf(m, __shfl_xor_sync(0xffffffffu, m, off));
    float e = expf(acc - m);
    float ssum = e;
    #pragma unroll
    for (int off = 8; off > 0; off >>= 1)
        ssum += __shfl_xor_sync(0xffffffffu, ssum, off);
    if (live) out[(size_t)node * FO + f] = acc - m - logf(ssum);
}

// ---------------------------------------------------------------------------
extern "C" void kernel_launch(void* const* d_in, const int* in_sizes, int n_in,
                              void* d_out, int out_size) {
    const float* x  = (const float*)d_in[0];
    const void*  ei = d_in[1];               // [2, E]; int32 or int64 (probed)
    const float* ew = (const float*)d_in[2];
    const float* W1 = (const float*)d_in[3];
    const float* b1 = (const float*)d_in[4];
    const float* W2 = (const float*)d_in[5];
    const float* b2 = (const float*)d_in[6];
    float*       out = (float*)d_out;

    int n = in_sizes[0] / FIN;   // 100000
    int E = in_sizes[2];         // 1600000

    probe_kernel<<<1, 1>>>(ei, E, n);
    init_kernel<<<(n + 255) / 256, 256>>>(n);
    cnt_kernel<<<(E + 255) / 256, 256>>>(ei, E);

    int nb = (n + SCAN_B - 1) / SCAN_B;      // 98
    scan1_kernel<<<nb, SCAN_B>>>(n);
    scan2_kernel<<<1, MAXBLK>>>(nb);
    scan3_kernel<<<(n + 255) / 256, 256>>>(n);

    build_kernel<<<(E + 255) / 256, 256>>>(ei, ew, E);

    long long tw = (long long)n * 32;  // one warp per node
    dinv_kernel<<<(int)((tw + 255) / 256), 256>>>(n);
    norm_kernel<<<(int)((tw + 255) / 256), 256>>>(n);

    gemm1_kernel<<<(n + 15) / 16, 256>>>(x, W1, n);

    agg1_kernel<<<(int)((tw + 255) / 256), 256>>>(b1, n);

    gemm2_kernel<<<(n + 255) / 256, 256>>>(W2, n);

    long long t2 = (long long)n * 16;
    agg2_kernel<<<(int)((t2 + 255) / 256), 256>>>(b2, out, n);
}

// round 7
// speedup vs baseline: 1.7702x; 1.0824x over previous
#include <cuda_runtime.h>

#define MAXN 100000
#define MAXE 1600000
#define FIN 128
#define FH 64
#define FO 16
#define SCAN_B 1024
#define MAXBLK 128   // >= ceil(MAXN/SCAN_B)
#define G1_ROWS 64
#define G1_THREADS 512
#define G1_SMEM ((FIN * FH + G1_ROWS * FIN) * 4)  // 32KB + 32KB = 64KB

// Scratch (device globals: allocation-free)
__device__ int    g_is64;            // 1 if edge_index is int64, 0 if int32
__device__ float  g_dinv[MAXN];
__device__ int    g_cnt[MAXN];       // in-degree (edges only)
__device__ int    g_rowstart[MAXN];  // CSR row offsets (by dst)
__device__ int    g_cursor[MAXN];    // fill cursors
__device__ int    g_blocksum[MAXBLK];
__device__ int    g_csrc[MAXE];      // CSR: source node per slot
__device__ float  g_cnorm[MAXE];     // CSR: raw ew, then final norm
__device__ float4 g_h1[(size_t)MAXN * (FH / 4)];  // x @ W1        [n][64]
__device__ float4 g_z [(size_t)MAXN * (FH / 4)];  // relu(agg1)    [n][64]
__device__ float4 g_h2[(size_t)MAXN * (FO / 4)];  // z @ W2        [n][16]

__device__ __forceinline__ int edge_src(const void* ei, int E, int e) {
    return g_is64 ? (int)((const long long*)ei)[e] : ((const int*)ei)[e];
}
__device__ __forceinline__ int edge_dst(const void* ei, int E, int e) {
    return g_is64 ? (int)((const long long*)ei)[(size_t)E + e]
                  : ((const int*)ei)[(size_t)E + e];
}

// ---------------------------------------------------------------------------
__global__ void probe_kernel(const void* ei, int E, int n) {
    if (threadIdx.x != 0 || blockIdx.x != 0) return;
    const long long* p = (const long long*)ei;
    int ok64 = 1;
    int m = E < 64 ? E : 64;
    for (int i = 0; i < m; i++) {
        long long v = p[i];
        long long w = p[(size_t)E + i];
        if (v < 0 || v >= n || w < 0 || w >= n) { ok64 = 0; break; }
    }
    g_is64 = ok64;
}

__global__ void init_kernel(int n) {
    int i = blockIdx.x * blockDim.x + threadIdx.x;
    if (i < n) g_cnt[i] = 0;
}

__global__ void cnt_kernel(const void* __restrict__ ei, int E) {
    int e = blockIdx.x * blockDim.x + threadIdx.x;
    if (e >= E) return;
    atomicAdd(&g_cnt[edge_dst(ei, E, e)], 1);
}

// ---------------------------------------------------------------------------
// h1 = x @ W1   (n x 128 @ 128 x 64), 64 rows/block, 512 threads, 64KB dyn smem
// launched 4th so ncu profiles it
// ---------------------------------------------------------------------------
__global__ void gemm1_kernel(const float* __restrict__ x,
                             const float* __restrict__ W1, int n) {
    extern __shared__ float smem[];
    float* sW = smem;                 // [128][64]
    float* sx = smem + FIN * FH;      // [64][128]
    int t = threadIdx.x;

    const float4* w4 = (const float4*)W1;
    float4* sw4 = (float4*)sW;
    #pragma unroll
    for (int i = t; i < FIN * FH / 4; i += G1_THREADS) sw4[i] = w4[i];

    int rowBase = blockIdx.x * G1_ROWS;
    #pragma unroll
    for (int i = t; i < G1_ROWS * FIN / 4; i += G1_THREADS) {
        int r = i / (FIN / 4), c = i % (FIN / 4);
        int row = rowBase + r;
        float4 val = (row < n) ? ((const float4*)(x + (size_t)row * FIN))[c]
                               : make_float4(0.f, 0.f, 0.f, 0.f);
        ((float4*)(sx + r * FIN))[c] = val;
    }
    __syncthreads();

    int col = t & 63;
    int rg = t >> 6;  // 0..7 -> rows rg*8 .. rg*8+7
    float acc[8];
    #pragma unroll
    for (int i = 0; i < 8; i++) acc[i] = 0.f;
    #pragma unroll
    for (int k4 = 0; k4 < FIN / 4; k4++) {
        float w0 = sW[(k4 * 4 + 0) * FH + col];
        float w1 = sW[(k4 * 4 + 1) * FH + col];
        float w2 = sW[(k4 * 4 + 2) * FH + col];
        float w3 = sW[(k4 * 4 + 3) * FH + col];
        #pragma unroll
        for (int i = 0; i < 8; i++) {
            float4 xv = ((const float4*)(sx + (rg * 8 + i) * FIN))[k4];
            acc[i] += xv.x * w0 + xv.y * w1 + xv.z * w2 + xv.w * w3;
        }
    }
    float* h1 = (float*)g_h1;
    #pragma unroll
    for (int i = 0; i < 8; i++) {
        int row = rowBase + rg * 8 + i;
        if (row < n) h1[(size_t)row * FH + col] = acc[i];
    }
}

// ---------------------------------------------------------------------------
// hierarchical exclusive scan of g_cnt -> g_rowstart (+ cursor copy)
// ---------------------------------------------------------------------------
__global__ void scan1_kernel(int n) {
    __shared__ int s[SCAN_B];
    int t = threadIdx.x;
    int gid = blockIdx.x * SCAN_B + t;
    int v = (gid < n) ? g_cnt[gid] : 0;
    s[t] = v;
    __syncthreads();
    #pragma unroll
    for (int off = 1; off < SCAN_B; off <<= 1) {
        int u = (t >= off) ? s[t - off] : 0;
        __syncthreads();
        s[t] += u;
        __syncthreads();
    }
    if (gid < n) g_rowstart[gid] = s[t] - v;
    if (t == SCAN_B - 1) g_blocksum[blockIdx.x] = s[t];
}

__global__ void scan2_kernel(int nb) {
    __shared__ int s[MAXBLK];
    int t = threadIdx.x;
    int v = (t < nb) ? g_blocksum[t] : 0;
    s[t] = v;
    __syncthreads();
    #pragma unroll
    for (int off = 1; off < MAXBLK; off <<= 1) {
        int u = (t >= off) ? s[t - off] : 0;
        __syncthreads();
        s[t] += u;
        __syncthreads();
    }
    if (t < nb) g_blocksum[t] = s[t] - v;
}

__global__ void scan3_kernel(int n) {
    int gid = blockIdx.x * blockDim.x + threadIdx.x;
    if (gid >= n) return;
    int r = g_rowstart[gid] + g_blocksum[gid >> 10];
    g_rowstart[gid] = r;
    g_cursor[gid] = r;
}

// scatter edges into CSR slots (int atomic cursors); store src + raw weight
__global__ void build_kernel(const void* __restrict__ ei,
                             const float* __restrict__ ew, int E) {
    int e = blockIdx.x * blockDim.x + threadIdx.x;
    if (e >= E) return;
    int s = edge_src(ei, E, e);
    int d = edge_dst(ei, E, e);
    int pos = atomicAdd(&g_cursor[d], 1);
    g_csrc[pos] = s;
    g_cnorm[pos] = ew[e];
}

// warp per node: deg = 1 (self-loop) + sum of edge weights -> dinv
__global__ void dinv_kernel(int n) {
    int warp = (blockIdx.x * blockDim.x + threadIdx.x) >> 5;
    if (warp >= n) return;
    int lane = threadIdx.x & 31;
    int start = g_rowstart[warp];
    int end = start + g_cnt[warp];
    float s = 0.f;
    for (int j = start + lane; j < end; j += 32) s += g_cnorm[j];
    #pragma unroll
    for (int off = 16; off > 0; off >>= 1)
        s += __shfl_xor_sync(0xffffffffu, s, off);
    if (lane == 0) g_dinv[warp] = rsqrtf(1.0f + s);
}

// warp per node: cnorm[j] = dinv[src] * ew * dinv[dst]
__global__ void norm_kernel(int n) {
    int warp = (blockIdx.x * blockDim.x + threadIdx.x) >> 5;
    if (warp >= n) return;
    int lane = threadIdx.x & 31;
    float dd = g_dinv[warp];
    int start = g_rowstart[warp];
    int end = start + g_cnt[warp];
    for (int j = start + lane; j < end; j += 32)
        g_cnorm[j] = g_dinv[g_csrc[j]] * g_cnorm[j] * dd;
}

// ---------------------------------------------------------------------------
// agg1: one warp per dst node. Lanes own 2 features (float2 of the 64).
// 8-deep edge unroll for MLP.
// ---------------------------------------------------------------------------
__global__ void agg1_kernel(const float* __restrict__ b1, int n) {
    int warp = (blockIdx.x * blockDim.x + threadIdx.x) >> 5;
    if (warp >= n) return;
    int lane = threadIdx.x & 31;
    const float2* h1 = (const float2*)g_h1;   // [n][32] float2
    int start = g_rowstart[warp];
    int end = start + g_cnt[warp];
    float2 acc = make_float2(0.f, 0.f);

    int j = start;
    for (; j + 8 <= end; j += 8) {
        int   s0 = g_csrc[j],  s1 = g_csrc[j+1],  s2 = g_csrc[j+2],  s3 = g_csrc[j+3];
        int   s4 = g_csrc[j+4], s5 = g_csrc[j+5], s6 = g_csrc[j+6], s7 = g_csrc[j+7];
        float n0 = g_cnorm[j],   n1 = g_cnorm[j+1], n2 = g_cnorm[j+2], n3 = g_cnorm[j+3];
        float n4 = g_cnorm[j+4], n5 = g_cnorm[j+5], n6 = g_cnorm[j+6], n7 = g_cnorm[j+7];
        float2 v0 = h1[(size_t)s0 * 32 + lane];
        float2 v1 = h1[(size_t)s1 * 32 + lane];
        float2 v2 = h1[(size_t)s2 * 32 + lane];
        float2 v3 = h1[(size_t)s3 * 32 + lane];
        float2 v4 = h1[(size_t)s4 * 32 + lane];
        float2 v5 = h1[(size_t)s5 * 32 + lane];
        float2 v6 = h1[(size_t)s6 * 32 + lane];
        float2 v7 = h1[(size_t)s7 * 32 + lane];
        acc.x += n0 * v0.x + n1 * v1.x + n2 * v2.x + n3 * v3.x
               + n4 * v4.x + n5 * v5.x + n6 * v6.x + n7 * v7.x;
        acc.y += n0 * v0.y + n1 * v1.y + n2 * v2.y + n3 * v3.y
               + n4 * v4.y + n5 * v5.y + n6 * v6.y + n7 * v7.y;
    }
    for (; j < end; j++) {
        int s = g_csrc[j];
        float nm = g_cnorm[j];
        float2 v = h1[(size_t)s * 32 + lane];
        acc.x += nm * v.x;
        acc.y += nm * v.y;
    }
    float dv = g_dinv[warp];
    float self = dv * dv;
    float2 hs = h1[(size_t)warp * 32 + lane];
    acc.x += self * hs.x;
    acc.y += self * hs.y;
    acc.x = fmaxf(acc.x + b1[lane * 2 + 0], 0.f);
    acc.y = fmaxf(acc.y + b1[lane * 2 + 1], 0.f);
    ((float2*)g_z)[(size_t)warp * 32 + lane] = acc;
}

// ---------------------------------------------------------------------------
// h2 = z @ W2  (64 -> 16), one thread per node, W2 in SMEM
// ---------------------------------------------------------------------------
__global__ void gemm2_kernel(const float* __restrict__ W2, int n) {
    __shared__ float sW[FH * FO];  // 4 KB
    for (int i = threadIdx.x; i < FH * FO; i += blockDim.x) sW[i] = W2[i];
    __syncthreads();

    int nn = blockIdx.x * blockDim.x + threadIdx.x;
    if (nn >= n) return;
    const float4* z4 = &g_z[(size_t)nn * (FH / 4)];
    float acc[FO];
    #pragma unroll
    for (int j = 0; j < FO; j++) acc[j] = 0.f;
    #pragma unroll
    for (int k4 = 0; k4 < FH / 4; k4++) {
        float4 zv = z4[k4];
        #pragma unroll
        for (int j = 0; j < FO; j++) {
            acc[j] += zv.x * sW[(k4 * 4 + 0) * FO + j];
            acc[j] += zv.y * sW[(k4 * 4 + 1) * FO + j];
            acc[j] += zv.z * sW[(k4 * 4 + 2) * FO + j];
            acc[j] += zv.w * sW[(k4 * 4 + 3) * FO + j];
        }
    }
    float4* o4 = &g_h2[(size_t)nn * (FO / 4)];
    o4[0] = make_float4(acc[0], acc[1], acc[2], acc[3]);
    o4[1] = make_float4(acc[4], acc[5], acc[6], acc[7]);
    o4[2] = make_float4(acc[8], acc[9], acc[10], acc[11]);
    o4[3] = make_float4(acc[12], acc[13], acc[14], acc[15]);
}

// ---------------------------------------------------------------------------
// agg2 + log_softmax: half-warp (16 lanes) per node, one feature per lane.
// ---------------------------------------------------------------------------
__global__ void agg2_kernel(const float* __restrict__ b2,
                            float* __restrict__ out, int n) {
    int gid = blockIdx.x * blockDim.x + threadIdx.x;
    int node = gid >> 4;
    bool live = node < n;
    if (!live) node = 0;
    int f = gid & 15;
    const float* h2 = (const float*)g_h2;   // [n][16]
    int start = g_rowstart[node];
    int end = start + g_cnt[node];
    float acc = 0.f;

    int j = start;
    for (; j + 4 <= end; j += 4) {
        int   s0 = g_csrc[j],  s1 = g_csrc[j+1],  s2 = g_csrc[j+2],  s3 = g_csrc[j+3];
        float n0 = g_cnorm[j], n1 = g_cnorm[j+1], n2 = g_cnorm[j+2], n3 = g_cnorm[j+3];
        acc += n0 * h2[(size_t)s0 * FO + f] + n1 * h2[(size_t)s1 * FO + f]
             + n2 * h2[(size_t)s2 * FO + f] + n3 * h2[(size_t)s3 * FO + f];
    }
    for (; j < end; j++) {
        acc += g_cnorm[j] * h2[(size_t)g_csrc[j] * FO + f];
    }
    float dv = g_dinv[node];
    acc += dv * dv * h2[(size_t)node * FO + f] + b2[f];

    float m = acc;
    #pragma unroll
    for (int off = 8; off > 0; off >>= 1)
        m = fmaxf(m, __shfl_xor_sync(0xffffffffu, m, off));
    float e = expf(acc - m);
    float ssum = e;
    #pragma unroll
    for (int off = 8; off > 0; off >>= 1)
        ssum += __shfl_xor_sync(0xffffffffu, ssum, off);
    if (live) out[(size_t)node * FO + f] = acc - m - logf(ssum);
}

// ---------------------------------------------------------------------------
extern "C" void kernel_launch(void* const* d_in, const int* in_sizes, int n_in,
                              void* d_out, int out_size) {
    const float* x  = (const float*)d_in[0];
    const void*  ei = d_in[1];               // [2, E]; int32 or int64 (probed)
    const float* ew = (const float*)d_in[2];
    const float* W1 = (const float*)d_in[3];
    const float* b1 = (const float*)d_in[4];
    const float* W2 = (const float*)d_in[5];
    const float* b2 = (const float*)d_in[6];
    float*       out = (float*)d_out;

    int n = in_sizes[0] / FIN;   // 100000
    int E = in_sizes[2];         // 1600000

    cudaFuncSetAttribute(gemm1_kernel,
                         cudaFuncAttributeMaxDynamicSharedMemorySize, G1_SMEM);

    probe_kernel<<<1, 1>>>(ei, E, n);
    init_kernel<<<(n + 255) / 256, 256>>>(n);
    cnt_kernel<<<(E + 255) / 256, 256>>>(ei, E);

    // 4th launch -> profiled by ncu
    gemm1_kernel<<<(n + G1_ROWS - 1) / G1_ROWS, G1_THREADS, G1_SMEM>>>(x, W1, n);

    int nb = (n + SCAN_B - 1) / SCAN_B;      // 98
    scan1_kernel<<<nb, SCAN_B>>>(n);
    scan2_kernel<<<1, MAXBLK>>>(nb);
    scan3_kernel<<<(n + 255) / 256, 256>>>(n);

    build_kernel<<<(E + 255) / 256, 256>>>(ei, ew, E);

    long long tw = (long long)n * 32;  // one warp per node
    dinv_kernel<<<(int)((tw + 255) / 256), 256>>>(n);
    norm_kernel<<<(int)((tw + 255) / 256), 256>>>(n);

    agg1_kernel<<<(int)((tw + 255) / 256), 256>>>(b1, n);

    gemm2_kernel<<<(n + 255) / 256, 256>>>(W2, n);

    long long t2 = (long long)n * 16;
    agg2_kernel<<<(int)((t2 + 255) / 256), 256>>>(b2, out, n);
}